// round 8
// baseline (speedup 1.0000x reference)
#include <cuda_runtime.h>

#define A_N 100000
#define B_N 200000
#define M_N 50000
#define H_N 128
#define NMOL_N 4000
#define MAXNB 8
#define FA 35
#define FB 40

typedef unsigned long long u64;

// Scratch (device globals — no allocations allowed)
__device__ __align__(128) float g_gm0[(size_t)B_N * H_N];
__device__ __align__(128) float g_gm1[(size_t)B_N * H_N];
__device__ __align__(128) float g_binput[(size_t)B_N * H_N];
__device__ __align__(128) float g_ah[(size_t)A_N * H_N];

// ---- packed f32x2 helpers (FFMA2 path; ptxas only emits it from PTX) ------
__device__ __forceinline__ u64 pk(float lo, float hi) {
    u64 r; asm("mov.b64 %0, {%1, %2};" : "=l"(r) : "f"(lo), "f"(hi)); return r;
}
__device__ __forceinline__ void upk(u64 v, float& lo, float& hi) {
    asm("mov.b64 {%0, %1}, %2;" : "=f"(lo), "=f"(hi) : "l"(v));
}
__device__ __forceinline__ void fma2(u64& d, u64 a, u64 b) {
    asm("fma.rn.f32x2 %0, %1, %2, %3;" : "=l"(d) : "l"(a), "l"(b), "l"(d));
}

// ---------------------------------------------------------------------------
// Partial 64-row x 128-col tile GEMM over k4 steps [K4B, K4E), packed f32x2.
// acc[2*rr+0] = cols (4tx+0,4tx+1), acc[2*rr+1] = cols (4tx+2,4tx+3).
// Same FMA order per output as the scalar version -> bit-identical results.
// ---------------------------------------------------------------------------
template <int K4B, int K4E, int XS4>
__device__ __forceinline__ void gemm_part(const float* sW, const float* sX,
                                          int wy, int tx, u64 acc[16]) {
    const float4* w4 = (const float4*)sW;
    const float4* x4 = (const float4*)sX;
#pragma unroll
    for (int k4 = K4B; k4 < K4E; k4++) {
        u64 w01[4], w23[4];
#pragma unroll
        for (int kk = 0; kk < 4; kk++) {
            float4 wv = w4[(k4 * 4 + kk) * 32 + tx];
            w01[kk] = pk(wv.x, wv.y);
            w23[kk] = pk(wv.z, wv.w);
        }
#pragma unroll
        for (int rr = 0; rr < 8; rr++) {
            float4 xv = x4[(wy + rr * 8) * XS4 + k4];
            u64 xs;
            xs = pk(xv.x, xv.x); fma2(acc[2 * rr], xs, w01[0]); fma2(acc[2 * rr + 1], xs, w23[0]);
            xs = pk(xv.y, xv.y); fma2(acc[2 * rr], xs, w01[1]); fma2(acc[2 * rr + 1], xs, w23[1]);
            xs = pk(xv.z, xv.z); fma2(acc[2 * rr], xs, w01[2]); fma2(acc[2 * rr + 1], xs, w23[2]);
            xs = pk(xv.w, xv.w); fma2(acc[2 * rr], xs, w01[3]); fma2(acc[2 * rr + 1], xs, w23[3]);
        }
    }
}

// Issue 8 float4 gather loads (4 neighbors x 32B) at float offset k0.
__device__ __forceinline__ void g_issue(const float* const* pb, int k0, float4 v[8]) {
#pragma unroll
    for (int j = 0; j < 4; j++) {
        const float4* p4 = (const float4*)(pb[j] + k0);
        v[2 * j] = p4[0];
        v[2 * j + 1] = p4[1];
    }
}
__device__ __forceinline__ void g_sum(const float4 v[8], float4& s0, float4& s1) {
#pragma unroll
    for (int j = 0; j < 4; j++) {
        s0.x += v[2 * j].x; s0.y += v[2 * j].y; s0.z += v[2 * j].z; s0.w += v[2 * j].w;
        s1.x += v[2 * j + 1].x; s1.y += v[2 * j + 1].y;
        s1.z += v[2 * j + 1].z; s1.w += v[2 * j + 1].w;
    }
}

// Precompute this thread's 8 neighbor base pointers (branchless concat select).
__device__ __forceinline__ void g_ptrs(const int* __restrict__ gp,
                                       const float* __restrict__ tree,
                                       const float* __restrict__ src,
                                       int q, const float* pb[MAXNB]) {
#pragma unroll
    for (int j = 0; j < MAXNB; j++) {
        int idx = gp[j];
        const float* p = (idx < M_N) ? (tree + (size_t)idx * H_N)
                                     : (src + (size_t)(idx - M_N) * H_N);
        pb[j] = p + q * 8;
    }
}

// ---------------------------------------------------------------------------
// binput = fbonds @ W_i ; g_gm0 = relu(binput)
// ---------------------------------------------------------------------------
__global__ __launch_bounds__(256, 2) void k_binput(const float* __restrict__ fbonds,
                                                   const float* __restrict__ Wi) {
    __shared__ __align__(16) float sW[FB * H_N];  // 20 KB
    __shared__ __align__(16) float sF[64 * FB];   // 10 KB
    int t = threadIdx.x;
    int tx = t & 31, wy = t >> 5;
    int b0 = blockIdx.x * 64;
    {
        const float4* src = (const float4*)Wi;
        float4* dst = (float4*)sW;
#pragma unroll
        for (int i = t; i < FB * H_N / 4; i += 256) dst[i] = src[i];
    }
    {
        const float4* src = (const float4*)(fbonds + (size_t)b0 * FB);
        float4* dst = (float4*)sF;
#pragma unroll
        for (int i = t; i < 64 * FB / 4; i += 256) dst[i] = __ldcs(src + i);
    }
    __syncthreads();
    u64 acc[16];
#pragma unroll
    for (int r = 0; r < 16; r++) acc[r] = pk(0.f, 0.f);
    gemm_part<0, FB / 4, FB / 4>(sW, sF, wy, tx, acc);
#pragma unroll
    for (int rr = 0; rr < 8; rr++) {
        size_t b = (size_t)(b0 + wy + rr * 8);
        float4 a;
        upk(acc[2 * rr], a.x, a.y);
        upk(acc[2 * rr + 1], a.z, a.w);
        ((float4*)g_binput)[b * 32 + tx] = a;
        float4 o = make_float4(fmaxf(a.x, 0.f), fmaxf(a.y, 0.f),
                               fmaxf(a.z, 0.f), fmaxf(a.w, 0.f));
        ((float4*)g_gm0)[b * 32 + tx] = o;  // next gather table: default policy
    }
}

// ---------------------------------------------------------------------------
// One MP iteration: dst = relu(binput + gather_sum(src) @ W_h)
// Software-pipelined: gather(c+1) loads issued before/within gemm(c).
// Double-buffered sW+sX, exactly 48 KB smem, one sync per chunk.
// ---------------------------------------------------------------------------
__global__ __launch_bounds__(256, 2) void k_iter(const float* __restrict__ tree,
                                                  const int* __restrict__ bgraph,
                                                  const float* __restrict__ Wh,
                                                  int srcsel) {
    __shared__ __align__(16) float sW[2][32 * H_N];  // 32 KB
    __shared__ __align__(16) float sX[2][64 * 32];   // 16 KB
    const float* src = srcsel ? g_gm1 : g_gm0;
    float* dst = srcsel ? g_gm0 : g_gm1;
    int t = threadIdx.x;
    int tx = t & 31, wy = t >> 5;
    int row = t >> 2, q = t & 3;
    int b0 = blockIdx.x * 64;

    const float* pb[MAXNB];
    g_ptrs(bgraph + (size_t)(b0 + row) * MAXNB, tree, src, q, pb);

    u64 acc[16];
#pragma unroll
    for (int r = 0; r < 16; r++) acc[r] = pk(0.f, 0.f);

    // prologue: gather chunk 0
    float4 s0 = {0.f, 0.f, 0.f, 0.f}, s1 = s0;
    {
        float4 v[8];
        g_issue(pb, 0, v);     g_sum(v, s0, s1);
        g_issue(pb + 4, 0, v); g_sum(v, s0, s1);
    }

#pragma unroll
    for (int c = 0; c < 4; c++) {
        int buf = c & 1;
        {   // publish gather(c) and stage W(c) into this chunk's buffers
            float4* o = (float4*)(sX[buf] + row * 32) + q * 2;
            o[0] = s0; o[1] = s1;
            const float4* wsrc = (const float4*)(Wh + (size_t)c * 32 * H_N);
            float4* wdst = (float4*)sW[buf];
#pragma unroll
            for (int i = 0; i < 4; i++) wdst[t + i * 256] = wsrc[t + i * 256];
        }
        __syncthreads();
        float4 va[8];
        int k0n = (c + 1) * 32;
        if (c < 3) g_issue(pb, k0n, va);                 // prefetch nb 0-3
        gemm_part<0, 4, 8>(sW[buf], sX[buf], wy, tx, acc);
        float4 t0 = {0.f, 0.f, 0.f, 0.f}, t1 = t0;
        if (c < 3) { g_sum(va, t0, t1); g_issue(pb + 4, k0n, va); }  // nb 4-7
        gemm_part<4, 8, 8>(sW[buf], sX[buf], wy, tx, acc);
        if (c < 3) { g_sum(va, t0, t1); s0 = t0; s1 = t1; }
    }
#pragma unroll
    for (int rr = 0; rr < 8; rr++) {
        size_t b = (size_t)(b0 + wy + rr * 8);
        float4 bi = __ldcs(((const float4*)g_binput) + b * 32 + tx);  // stream
        float4 a;
        upk(acc[2 * rr], a.x, a.y);
        upk(acc[2 * rr + 1], a.z, a.w);
        float4 o = make_float4(fmaxf(a.x + bi.x, 0.f), fmaxf(a.y + bi.y, 0.f),
                               fmaxf(a.z + bi.z, 0.f), fmaxf(a.w + bi.w, 0.f));
        ((float4*)dst)[b * 32 + tx] = o;  // next iter's gather table: default
    }
}

// ---------------------------------------------------------------------------
// Atom stage: ah = relu([fatoms, gather_sum(final msg)] @ W_o + b_o)
// F chunk (36 cols) then 4 pipelined gather chunks. Single sW (two syncs/iter)
// + double sX to stay under the 48 KB static smem limit.
// ---------------------------------------------------------------------------
__global__ __launch_bounds__(256, 2) void k_atom(const float* __restrict__ fatoms,
                                                  const float* __restrict__ tree,
                                                  const int* __restrict__ agraph,
                                                  const float* __restrict__ Wo,
                                                  const float* __restrict__ bo) {
    __shared__ __align__(16) float sW[36 * H_N];     // 18 KB
    __shared__ __align__(16) float sX[2][64 * 36];   // 18 KB
    int t = threadIdx.x;
    int tx = t & 31, wy = t >> 5;
    int row = t >> 2, q = t & 3;
    int a0 = blockIdx.x * 64;
    bool rvalid = (a0 + row) < A_N;

    const float* pb[MAXNB];
    g_ptrs(agraph + (size_t)(rvalid ? (a0 + row) : 0) * MAXNB, tree, g_gm0, q, pb);

    float4 bov = ((const float4*)bo)[tx];
    u64 acc[16];
#pragma unroll
    for (int rr = 0; rr < 8; rr++) {
        acc[2 * rr] = pk(bov.x, bov.y);      // bias folded in
        acc[2 * rr + 1] = pk(bov.z, bov.w);
    }

    // F chunk: Wo rows 0..34 (+zero row 35) and fatoms into buf 0
    {
        const float4* wsrc = (const float4*)Wo;
        float4* wdst = (float4*)sW;
        float4 z4 = make_float4(0.f, 0.f, 0.f, 0.f);
#pragma unroll
        for (int i = t; i < 36 * H_N / 4; i += 256)
            wdst[i] = (i < FA * H_N / 4) ? wsrc[i] : z4;
        for (int i = t; i < 64 * 36; i += 256) {
            int r = i / 36;
            int c = i - r * 36;
            int a = a0 + r;
            sX[0][r * 36 + c] = (c < FA && a < A_N) ? __ldcs(fatoms + (size_t)a * FA + c) : 0.f;
        }
    }
    __syncthreads();
    // overlap gather(chunk 0) with the F gemm
    float4 s0 = {0.f, 0.f, 0.f, 0.f}, s1 = s0;
    {
        float4 va[8];
        g_issue(pb, 0, va);
        gemm_part<0, 5, 9>(sW, sX[0], wy, tx, acc);
        g_sum(va, s0, s1);
        g_issue(pb + 4, 0, va);
        gemm_part<5, 9, 9>(sW, sX[0], wy, tx, acc);
        g_sum(va, s0, s1);
    }

#pragma unroll
    for (int c = 0; c < 4; c++) {
        int buf = (c + 1) & 1;
        {
            float4* o = (float4*)(sX[buf] + row * 32) + q * 2;
            o[0] = s0; o[1] = s1;
        }
        __syncthreads();  // previous gemm done reading sW
        {
            const float4* wsrc = (const float4*)(Wo + (size_t)(FA + c * 32) * H_N);
            float4* wdst = (float4*)sW;
#pragma unroll
            for (int i = 0; i < 4; i++) wdst[t + i * 256] = wsrc[t + i * 256];
        }
        __syncthreads();  // sW(c) ready
        float4 va[8];
        int k0n = (c + 1) * 32;
        if (c < 3) g_issue(pb, k0n, va);
        gemm_part<0, 4, 8>(sW, sX[buf], wy, tx, acc);
        float4 t0 = {0.f, 0.f, 0.f, 0.f}, t1 = t0;
        if (c < 3) { g_sum(va, t0, t1); g_issue(pb + 4, k0n, va); }
        gemm_part<4, 8, 8>(sW, sX[buf], wy, tx, acc);
        if (c < 3) { g_sum(va, t0, t1); s0 = t0; s1 = t1; }
    }
#pragma unroll
    for (int rr = 0; rr < 8; rr++) {
        int a = a0 + wy + rr * 8;
        if (a < A_N) {
            float4 v;
            upk(acc[2 * rr], v.x, v.y);
            upk(acc[2 * rr + 1], v.z, v.w);
            float4 o = make_float4(fmaxf(v.x, 0.f), fmaxf(v.y, 0.f),
                                   fmaxf(v.z, 0.f), fmaxf(v.w, 0.f));
            __stcs(((float4*)g_ah) + (size_t)a * 32 + tx, o);  // consumed once
        }
    }
}

// ---------------------------------------------------------------------------
// Segment mean: mol_id sorted -> block m binary-searches its [lo,hi) range.
// Deterministic (no fp32 atomics).
// ---------------------------------------------------------------------------
__global__ __launch_bounds__(128) void k_mol(const int* __restrict__ mol_id,
                                             float* __restrict__ out) {
    int m = blockIdx.x;
    int h = threadIdx.x;
    __shared__ int sb[2];
    if (h < 2) {
        int v = m + h;
        int lo = 0, hi = A_N;
        while (lo < hi) {
            int mid = (lo + hi) >> 1;
            if (mol_id[mid] < v) lo = mid + 1;
            else hi = mid;
        }
        sb[h] = lo;
    }
    __syncthreads();
    int lo = sb[0], hi = sb[1];
    float s = 0.f;
    for (int a = lo; a < hi; a++) s += __ldcs(g_ah + (size_t)a * H_N + h);
    out[(size_t)m * H_N + h] = s / fmaxf((float)(hi - lo), 1.f);
}

// ---------------------------------------------------------------------------
extern "C" void kernel_launch(void* const* d_in, const int* in_sizes, int n_in,
                              void* d_out, int out_size) {
    const float* fatoms = (const float*)d_in[0];
    const float* fbonds = (const float*)d_in[1];
    const float* tree   = (const float*)d_in[2];
    const int*   agraph = (const int*)d_in[3];
    const int*   bgraph = (const int*)d_in[4];
    const int*   mol_id = (const int*)d_in[5];
    const float* Wi     = (const float*)d_in[6];
    const float* Wh     = (const float*)d_in[7];
    const float* Wo     = (const float*)d_in[8];
    const float* bo     = (const float*)d_in[9];
    float* out = (float*)d_out;

    k_binput<<<B_N / 64, 256>>>(fbonds, Wi);
    k_iter<<<B_N / 64, 256>>>(tree, bgraph, Wh, 0);  // gm0 -> gm1
    k_iter<<<B_N / 64, 256>>>(tree, bgraph, Wh, 1);  // gm1 -> gm0
    k_iter<<<B_N / 64, 256>>>(tree, bgraph, Wh, 0);  // gm0 -> gm1
    k_iter<<<B_N / 64, 256>>>(tree, bgraph, Wh, 1);  // gm1 -> gm0 (final)
    k_atom<<<(A_N + 63) / 64, 256>>>(fatoms, tree, agraph, Wo, bo);
    k_mol<<<NMOL_N, 128>>>(mol_id, out);
}

// round 9
// speedup vs baseline: 1.1341x; 1.1341x over previous
#include <cuda_runtime.h>
#include <cuda_bf16.h>

#define A_N 100000
#define B_N 200000
#define M_N 50000
#define H_N 128
#define NMOL_N 4000
#define MAXNB 8
#define FA 35
#define FB 40

// Scratch (device globals — no allocations allowed)
// Message tables in bf16: tree copy 12.8 MB + 2x51 MB ping-pong -> all L2-resident.
__device__ __align__(128) __nv_bfloat16 g_tr[(size_t)M_N * H_N];
__device__ __align__(128) __nv_bfloat16 g_gm0[(size_t)B_N * H_N];
__device__ __align__(128) __nv_bfloat16 g_gm1[(size_t)B_N * H_N];
__device__ __align__(128) float g_binput[(size_t)B_N * H_N];  // fp32 (accuracy anchor)
__device__ __align__(128) float g_ah[(size_t)A_N * H_N];

// pack fp32x4 -> bf16x4 (rn)
__device__ __forceinline__ uint2 to_bf4(float4 o) {
    __nv_bfloat162 lo = __float22bfloat162_rn(make_float2(o.x, o.y));
    __nv_bfloat162 hi = __float22bfloat162_rn(make_float2(o.z, o.w));
    uint2 r;
    r.x = *(unsigned*)&lo;
    r.y = *(unsigned*)&hi;
    return r;
}

// ---------------------------------------------------------------------------
// Partial 64-row x 128-col tile GEMM over k4 steps [K4B, K4E)  (fp32 scalar).
// tx -> h columns tx*4.. ; wy -> rows {wy, wy+8, ..., wy+56}.
// ---------------------------------------------------------------------------
template <int K4B, int K4E, int XS4>
__device__ __forceinline__ void gemm_part(const float* sW, const float* sX,
                                          int wy, int tx, float4 acc[8]) {
    const float4* w4 = (const float4*)sW;
    const float4* x4 = (const float4*)sX;
#pragma unroll
    for (int k4 = K4B; k4 < K4E; k4++) {
        float4 wv[4];
#pragma unroll
        for (int kk = 0; kk < 4; kk++) wv[kk] = w4[(k4 * 4 + kk) * 32 + tx];
#pragma unroll
        for (int rr = 0; rr < 8; rr++) {
            float4 xv = x4[(wy + rr * 8) * XS4 + k4];
            acc[rr].x = fmaf(xv.x, wv[0].x, acc[rr].x);
            acc[rr].y = fmaf(xv.x, wv[0].y, acc[rr].y);
            acc[rr].z = fmaf(xv.x, wv[0].z, acc[rr].z);
            acc[rr].w = fmaf(xv.x, wv[0].w, acc[rr].w);
            acc[rr].x = fmaf(xv.y, wv[1].x, acc[rr].x);
            acc[rr].y = fmaf(xv.y, wv[1].y, acc[rr].y);
            acc[rr].z = fmaf(xv.y, wv[1].z, acc[rr].z);
            acc[rr].w = fmaf(xv.y, wv[1].w, acc[rr].w);
            acc[rr].x = fmaf(xv.z, wv[2].x, acc[rr].x);
            acc[rr].y = fmaf(xv.z, wv[2].y, acc[rr].y);
            acc[rr].z = fmaf(xv.z, wv[2].z, acc[rr].z);
            acc[rr].w = fmaf(xv.z, wv[2].w, acc[rr].w);
            acc[rr].x = fmaf(xv.w, wv[3].x, acc[rr].x);
            acc[rr].y = fmaf(xv.w, wv[3].y, acc[rr].y);
            acc[rr].z = fmaf(xv.w, wv[3].z, acc[rr].z);
            acc[rr].w = fmaf(xv.w, wv[3].w, acc[rr].w);
        }
    }
}

// bf16 gather: 4 neighbors x 16B (8 cols) at column offset k0.
__device__ __forceinline__ void gb_issue(const __nv_bfloat16* const* pb, int k0,
                                         uint4 v[4]) {
#pragma unroll
    for (int j = 0; j < 4; j++) v[j] = *(const uint4*)(pb[j] + k0);
}
__device__ __forceinline__ void gb_sum(const uint4 v[4], float4& s0, float4& s1) {
#pragma unroll
    for (int j = 0; j < 4; j++) {
        float2 f;
        f = __bfloat1622float2(*(const __nv_bfloat162*)&v[j].x); s0.x += f.x; s0.y += f.y;
        f = __bfloat1622float2(*(const __nv_bfloat162*)&v[j].y); s0.z += f.x; s0.w += f.y;
        f = __bfloat1622float2(*(const __nv_bfloat162*)&v[j].z); s1.x += f.x; s1.y += f.y;
        f = __bfloat1622float2(*(const __nv_bfloat162*)&v[j].w); s1.z += f.x; s1.w += f.y;
    }
}

// Precompute this thread's 8 neighbor base pointers (branchless concat select).
__device__ __forceinline__ void g_ptrs(const int* __restrict__ gp,
                                       const __nv_bfloat16* __restrict__ src,
                                       int q, const __nv_bfloat16* pb[MAXNB]) {
#pragma unroll
    for (int j = 0; j < MAXNB; j++) {
        int idx = gp[j];
        const __nv_bfloat16* p = (idx < M_N) ? (g_tr + (size_t)idx * H_N)
                                             : (src + (size_t)(idx - M_N) * H_N);
        pb[j] = p + q * 8;
    }
}

// ---------------------------------------------------------------------------
// One-time: convert tree_message fp32 -> bf16 table.
// ---------------------------------------------------------------------------
__global__ __launch_bounds__(256) void k_tree(const float* __restrict__ tree) {
    int i = blockIdx.x * 256 + threadIdx.x;  // one float4 -> uint2 per thread
    float4 v = ((const float4*)tree)[i];
    ((uint2*)g_tr)[i] = to_bf4(v);
}

// ---------------------------------------------------------------------------
// binput = fbonds @ W_i (fp32) ; g_gm0 = bf16(relu(binput))
// ---------------------------------------------------------------------------
__global__ __launch_bounds__(256, 2) void k_binput(const float* __restrict__ fbonds,
                                                   const float* __restrict__ Wi) {
    __shared__ __align__(16) float sW[FB * H_N];  // 20 KB
    __shared__ __align__(16) float sF[64 * FB];   // 10 KB
    int t = threadIdx.x;
    int tx = t & 31, wy = t >> 5;
    int b0 = blockIdx.x * 64;
    {
        const float4* src = (const float4*)Wi;
        float4* dst = (float4*)sW;
#pragma unroll
        for (int i = t; i < FB * H_N / 4; i += 256) dst[i] = src[i];
    }
    {
        const float4* src = (const float4*)(fbonds + (size_t)b0 * FB);
        float4* dst = (float4*)sF;
#pragma unroll
        for (int i = t; i < 64 * FB / 4; i += 256) dst[i] = __ldcs(src + i);
    }
    __syncthreads();
    float4 acc[8];
#pragma unroll
    for (int r = 0; r < 8; r++) acc[r] = make_float4(0.f, 0.f, 0.f, 0.f);
    gemm_part<0, FB / 4, FB / 4>(sW, sF, wy, tx, acc);
#pragma unroll
    for (int rr = 0; rr < 8; rr++) {
        size_t b = (size_t)(b0 + wy + rr * 8);
        ((float4*)g_binput)[b * 32 + tx] = acc[rr];
        float4 o = make_float4(fmaxf(acc[rr].x, 0.f), fmaxf(acc[rr].y, 0.f),
                               fmaxf(acc[rr].z, 0.f), fmaxf(acc[rr].w, 0.f));
        ((uint2*)g_gm0)[b * 32 + tx] = to_bf4(o);  // bf16 gather table
    }
}

// ---------------------------------------------------------------------------
// One MP iteration: dst = bf16(relu(binput + gather_sum(src) @ W_h))
// Software-pipelined bf16 gathers; double-buffered sW+sX (48 KB).
// ---------------------------------------------------------------------------
__global__ __launch_bounds__(256, 2) void k_iter(const int* __restrict__ bgraph,
                                                  const float* __restrict__ Wh,
                                                  int srcsel) {
    __shared__ __align__(16) float sW[2][32 * H_N];  // 32 KB
    __shared__ __align__(16) float sX[2][64 * 32];   // 16 KB
    const __nv_bfloat16* src = srcsel ? g_gm1 : g_gm0;
    __nv_bfloat16* dst = srcsel ? g_gm0 : g_gm1;
    int t = threadIdx.x;
    int tx = t & 31, wy = t >> 5;
    int row = t >> 2, q = t & 3;
    int b0 = blockIdx.x * 64;

    const __nv_bfloat16* pb[MAXNB];
    g_ptrs(bgraph + (size_t)(b0 + row) * MAXNB, src, q, pb);

    float4 acc[8];
#pragma unroll
    for (int r = 0; r < 8; r++) acc[r] = make_float4(0.f, 0.f, 0.f, 0.f);

    // prologue: gather chunk 0
    float4 s0 = {0.f, 0.f, 0.f, 0.f}, s1 = s0;
    {
        uint4 v[4];
        gb_issue(pb, 0, v);     gb_sum(v, s0, s1);
        gb_issue(pb + 4, 0, v); gb_sum(v, s0, s1);
    }

#pragma unroll
    for (int c = 0; c < 4; c++) {
        int buf = c & 1;
        {   // publish gather(c) and stage W(c)
            float4* o = (float4*)(sX[buf] + row * 32) + q * 2;
            o[0] = s0; o[1] = s1;
            const float4* wsrc = (const float4*)(Wh + (size_t)c * 32 * H_N);
            float4* wdst = (float4*)sW[buf];
#pragma unroll
            for (int i = 0; i < 4; i++) wdst[t + i * 256] = wsrc[t + i * 256];
        }
        __syncthreads();
        uint4 va[4];
        int k0n = (c + 1) * 32;
        if (c < 3) gb_issue(pb, k0n, va);                // prefetch nb 0-3
        gemm_part<0, 4, 8>(sW[buf], sX[buf], wy, tx, acc);
        float4 t0 = {0.f, 0.f, 0.f, 0.f}, t1 = t0;
        if (c < 3) { gb_sum(va, t0, t1); gb_issue(pb + 4, k0n, va); }  // nb 4-7
        gemm_part<4, 8, 8>(sW[buf], sX[buf], wy, tx, acc);
        if (c < 3) { gb_sum(va, t0, t1); s0 = t0; s1 = t1; }
    }
#pragma unroll
    for (int rr = 0; rr < 8; rr++) {
        size_t b = (size_t)(b0 + wy + rr * 8);
        float4 bi = __ldcs(((const float4*)g_binput) + b * 32 + tx);  // stream
        float4 o = make_float4(fmaxf(acc[rr].x + bi.x, 0.f), fmaxf(acc[rr].y + bi.y, 0.f),
                               fmaxf(acc[rr].z + bi.z, 0.f), fmaxf(acc[rr].w + bi.w, 0.f));
        ((uint2*)dst)[b * 32 + tx] = to_bf4(o);  // next iter's gather table
    }
}

// ---------------------------------------------------------------------------
// Atom stage: ah = relu([fatoms, gather_sum(final msg)] @ W_o + b_o)  (fp32)
// F chunk (36 cols) then 4 pipelined bf16 gather chunks.
// ---------------------------------------------------------------------------
__global__ __launch_bounds__(256, 2) void k_atom(const float* __restrict__ fatoms,
                                                  const int* __restrict__ agraph,
                                                  const float* __restrict__ Wo,
                                                  const float* __restrict__ bo) {
    __shared__ __align__(16) float sW[36 * H_N];     // 18 KB
    __shared__ __align__(16) float sX[2][64 * 36];   // 18 KB
    int t = threadIdx.x;
    int tx = t & 31, wy = t >> 5;
    int row = t >> 2, q = t & 3;
    int a0 = blockIdx.x * 64;
    bool rvalid = (a0 + row) < A_N;

    const __nv_bfloat16* pb[MAXNB];
    g_ptrs(agraph + (size_t)(rvalid ? (a0 + row) : 0) * MAXNB, g_gm0, q, pb);

    float4 bov = ((const float4*)bo)[tx];
    float4 acc[8];
#pragma unroll
    for (int r = 0; r < 8; r++) acc[r] = bov;  // bias folded in

    // F chunk: Wo rows 0..34 (+zero row 35) and fatoms into buf 0
    {
        const float4* wsrc = (const float4*)Wo;
        float4* wdst = (float4*)sW;
        float4 z4 = make_float4(0.f, 0.f, 0.f, 0.f);
#pragma unroll
        for (int i = t; i < 36 * H_N / 4; i += 256)
            wdst[i] = (i < FA * H_N / 4) ? wsrc[i] : z4;
        for (int i = t; i < 64 * 36; i += 256) {
            int r = i / 36;
            int c = i - r * 36;
            int a = a0 + r;
            sX[0][r * 36 + c] = (c < FA && a < A_N) ? __ldcs(fatoms + (size_t)a * FA + c) : 0.f;
        }
    }
    __syncthreads();
    // overlap gather(chunk 0) with the F gemm
    float4 s0 = {0.f, 0.f, 0.f, 0.f}, s1 = s0;
    {
        uint4 va[4];
        gb_issue(pb, 0, va);
        gemm_part<0, 5, 9>(sW, sX[0], wy, tx, acc);
        gb_sum(va, s0, s1);
        gb_issue(pb + 4, 0, va);
        gemm_part<5, 9, 9>(sW, sX[0], wy, tx, acc);
        gb_sum(va, s0, s1);
    }

#pragma unroll
    for (int c = 0; c < 4; c++) {
        int buf = (c + 1) & 1;
        {
            float4* o = (float4*)(sX[buf] + row * 32) + q * 2;
            o[0] = s0; o[1] = s1;
        }
        __syncthreads();  // previous gemm done reading sW
        {
            const float4* wsrc = (const float4*)(Wo + (size_t)(FA + c * 32) * H_N);
            float4* wdst = (float4*)sW;
#pragma unroll
            for (int i = 0; i < 4; i++) wdst[t + i * 256] = wsrc[t + i * 256];
        }
        __syncthreads();  // sW(c) ready
        uint4 va[4];
        int k0n = (c + 1) * 32;
        if (c < 3) gb_issue(pb, k0n, va);
        gemm_part<0, 4, 8>(sW, sX[buf], wy, tx, acc);
        float4 t0 = {0.f, 0.f, 0.f, 0.f}, t1 = t0;
        if (c < 3) { gb_sum(va, t0, t1); gb_issue(pb + 4, k0n, va); }
        gemm_part<4, 8, 8>(sW, sX[buf], wy, tx, acc);
        if (c < 3) { gb_sum(va, t0, t1); s0 = t0; s1 = t1; }
    }
#pragma unroll
    for (int rr = 0; rr < 8; rr++) {
        int a = a0 + wy + rr * 8;
        if (a < A_N) {
            float4 o = make_float4(fmaxf(acc[rr].x, 0.f), fmaxf(acc[rr].y, 0.f),
                                   fmaxf(acc[rr].z, 0.f), fmaxf(acc[rr].w, 0.f));
            __stcs(((float4*)g_ah) + (size_t)a * 32 + tx, o);  // consumed once
        }
    }
}

// ---------------------------------------------------------------------------
// Segment mean: mol_id sorted -> block m binary-searches its [lo,hi) range.
// Deterministic (no fp32 atomics).
// ---------------------------------------------------------------------------
__global__ __launch_bounds__(128) void k_mol(const int* __restrict__ mol_id,
                                             float* __restrict__ out) {
    int m = blockIdx.x;
    int h = threadIdx.x;
    __shared__ int sb[2];
    if (h < 2) {
        int v = m + h;
        int lo = 0, hi = A_N;
        while (lo < hi) {
            int mid = (lo + hi) >> 1;
            if (mol_id[mid] < v) lo = mid + 1;
            else hi = mid;
        }
        sb[h] = lo;
    }
    __syncthreads();
    int lo = sb[0], hi = sb[1];
    float s = 0.f;
    for (int a = lo; a < hi; a++) s += __ldcs(g_ah + (size_t)a * H_N + h);
    out[(size_t)m * H_N + h] = s / fmaxf((float)(hi - lo), 1.f);
}

// ---------------------------------------------------------------------------
extern "C" void kernel_launch(void* const* d_in, const int* in_sizes, int n_in,
                              void* d_out, int out_size) {
    const float* fatoms = (const float*)d_in[0];
    const float* fbonds = (const float*)d_in[1];
    const float* tree   = (const float*)d_in[2];
    const int*   agraph = (const int*)d_in[3];
    const int*   bgraph = (const int*)d_in[4];
    const int*   mol_id = (const int*)d_in[5];
    const float* Wi     = (const float*)d_in[6];
    const float* Wh     = (const float*)d_in[7];
    const float* Wo     = (const float*)d_in[8];
    const float* bo     = (const float*)d_in[9];
    float* out = (float*)d_out;

    k_tree<<<M_N * H_N / 4 / 256, 256>>>(tree);       // fp32 -> bf16 table
    k_binput<<<B_N / 64, 256>>>(fbonds, Wi);
    k_iter<<<B_N / 64, 256>>>(bgraph, Wh, 0);  // gm0 -> gm1
    k_iter<<<B_N / 64, 256>>>(bgraph, Wh, 1);  // gm1 -> gm0
    k_iter<<<B_N / 64, 256>>>(bgraph, Wh, 0);  // gm0 -> gm1
    k_iter<<<B_N / 64, 256>>>(bgraph, Wh, 1);  // gm1 -> gm0 (final)
    k_atom<<<(A_N + 63) / 64, 256>>>(fatoms, agraph, Wo, bo);
    k_mol<<<NMOL_N, 128>>>(mol_id, out);
}